// round 15
// baseline (speedup 1.0000x reference)
#include <cuda_runtime.h>
#include <cuda_fp16.h>
#include <cstdint>

#define B_DIM 2
#define S_DIM 1024
#define E_DIM 1024
#define MH    16
#define DH    64
#define E3    3072

// Scratch (no cudaMalloc allowed) — fp16 hi/lo splits
__device__ __half g_qkvh[B_DIM * S_DIM * E3];
__device__ __half g_qkvl[B_DIM * S_DIM * E3];
__device__ __half g_xh[B_DIM * S_DIM * E_DIM];
__device__ __half g_xl[B_DIM * S_DIM * E_DIM];
__device__ __half g_wqh[E3 * E_DIM];
__device__ __half g_wql[E3 * E_DIM];
__device__ __half g_wph[E_DIM * E_DIM];
__device__ __half g_wpl[E_DIM * E_DIM];
__device__ __half g_hoh[B_DIM * S_DIM * E_DIM];
__device__ __half g_hol[B_DIM * S_DIM * E_DIM];
__device__ float g_opart[2 * B_DIM * S_DIM * E_DIM];
__device__ float g_pm[2 * 32 * S_DIM];
__device__ float g_pl[2 * 32 * S_DIM];

__device__ __forceinline__ uint32_t smem_u32(const void* p) {
    uint32_t a;
    asm("{ .reg .u64 t; cvta.to.shared.u64 t, %1; cvt.u32.u64 %0, t; }"
        : "=r"(a) : "l"(p));
    return a;
}

__device__ __forceinline__ uint32_t h2_bits(__half2 h) {
    return *reinterpret_cast<uint32_t*>(&h);
}

__device__ __forceinline__ void split2(float a, float b,
                                       uint32_t& hi, uint32_t& lo) {
    __half2 h = __float22half2_rn(make_float2(a, b));
    float2 hf = __half22float2(h);
    __half2 l = __float22half2_rn(make_float2(a - hf.x, b - hf.y));
    hi = h2_bits(h);
    lo = h2_bits(l);
}

__device__ __forceinline__ void mma16816(float* d, const uint32_t* a,
                                         uint32_t b0, uint32_t b1) {
    asm volatile(
        "mma.sync.aligned.m16n8k16.row.col.f32.f16.f16.f32 "
        "{%0,%1,%2,%3}, {%4,%5,%6,%7}, {%8,%9}, {%0,%1,%2,%3};"
        : "+f"(d[0]), "+f"(d[1]), "+f"(d[2]), "+f"(d[3])
        : "r"(a[0]), "r"(a[1]), "r"(a[2]), "r"(a[3]), "r"(b0), "r"(b1));
}

__device__ __forceinline__ void ldsm4(uint32_t* d, uint32_t addr) {
    asm volatile("ldmatrix.sync.aligned.m8n8.x4.shared.b16 {%0,%1,%2,%3}, [%4];"
        : "=r"(d[0]), "=r"(d[1]), "=r"(d[2]), "=r"(d[3]) : "r"(addr));
}

__device__ __forceinline__ void ldsm4t(uint32_t* d, uint32_t addr) {
    asm volatile("ldmatrix.sync.aligned.m8n8.x4.trans.shared.b16 {%0,%1,%2,%3}, [%4];"
        : "=r"(d[0]), "=r"(d[1]), "=r"(d[2]), "=r"(d[3]) : "r"(addr));
}

__device__ __forceinline__ void cpa16(uint32_t dst, const void* src) {
    asm volatile("cp.async.cg.shared.global [%0], [%1], 16;"
                 :: "r"(dst), "l"(src));
}

// ---------------------------------------------------------------------------
// Pre-pass: split fp32 -> fp16 hi/lo
// ---------------------------------------------------------------------------
__global__ void split_kernel(const float* __restrict__ in,
                             __half* __restrict__ hi,
                             __half* __restrict__ lo, int n4)
{
    int i = blockIdx.x * blockDim.x + threadIdx.x;
    if (i >= n4) return;
    float4 v = *(const float4*)(in + i * 4);
    uint32_t h0, l0, h1, l1;
    split2(v.x, v.y, h0, l0);
    split2(v.z, v.w, h1, l1);
    *(uint2*)(hi + i * 4) = make_uint2(h0, h1);
    *(uint2*)(lo + i * 4) = make_uint2(l0, l1);
}

// ---------------------------------------------------------------------------
// HMMA GEMM on pre-split fp16 (3-product). CTA tile 64x128, 8 warps (2x4),
// warp tile 32x32, K chunk 32, 2-stage cp.async pipeline, 3 CTAs/SM.
// If Ch != nullptr, writes fp16 hi/lo output; else fp32 to C.
// ---------------------------------------------------------------------------
#define RSTR  80
#define ATSZ  (64 * RSTR)      /* 5120  */
#define BTSZ  (128 * RSTR)     /* 10240 */
#define OFF_AL ATSZ            /* 5120  */
#define OFF_BH (2 * ATSZ)      /* 10240 */
#define OFF_BL (2 * ATSZ + BTSZ) /* 20480 */
#define SSTG  (2 * ATSZ + 2 * BTSZ)  /* 30720 per stage */

__global__ __launch_bounds__(256, 3) void gemm_bf(
    const __half* __restrict__ Ah_, const __half* __restrict__ Al_,
    const __half* __restrict__ Wh_, const __half* __restrict__ Wl_,
    float* __restrict__ C,
    __half* __restrict__ Ch, __half* __restrict__ Cl,
    int Nn, int Kn)
{
    extern __shared__ char smem[];
    uint32_t sb = smem_u32(smem);

    int tid = threadIdx.x;
    int lane = tid & 31, wid = tid >> 5;
    int wm = wid >> 2, wn = wid & 3;      // warp grid 2(m) x 4(n)
    int g = lane >> 2, t = lane & 3;
    int row0 = blockIdx.y * 64;
    int col0 = blockIdx.x * 128;

    int qm = lane >> 3, rm = lane & 7;
    uint32_t aOff = (uint32_t)(((qm & 1) * 8 + rm) * RSTR + (qm >> 1) * 16);
    uint32_t bOff = (uint32_t)(((qm >> 1) * 8 + rm) * RSTR + (qm & 1) * 16);

    float acc[2][4][4];
#pragma unroll
    for (int mt = 0; mt < 2; mt++)
#pragma unroll
        for (int j = 0; j < 4; j++)
#pragma unroll
            for (int q = 0; q < 4; q++) acc[mt][j][q] = 0.0f;

    // fill mapping: A rows 64 (threads 0..127), B rows 128 (all 256 threads)
    int rB = tid >> 1;
    int half_ = tid & 1;
    int rA = rB & 63;
    const char* srcAh = (const char*)(Ah_ + (size_t)(row0 + rA) * Kn) + half_ * 32;
    const char* srcAl = (const char*)(Al_ + (size_t)(row0 + rA) * Kn) + half_ * 32;
    const char* srcWh = (const char*)(Wh_ + (size_t)(col0 + rB) * Kn) + half_ * 32;
    const char* srcWl = (const char*)(Wl_ + (size_t)(col0 + rB) * Kn) + half_ * 32;
    uint32_t dstOffA = (uint32_t)(rA * RSTR + half_ * 32);
    uint32_t dstOffB = (uint32_t)(rB * RSTR + half_ * 32);
    bool doA = (tid < 128);

    uint32_t aRow0 = (uint32_t)((wm * 32) * RSTR);
    uint32_t bRow0 = (uint32_t)((wn * 32) * RSTR);

    int nChunks = Kn >> 5;

    // prologue: prefetch chunk 0 into stage 0
    {
        if (doA) {
            uint32_t d = sb + dstOffA;
            cpa16(d, srcAh);              cpa16(d + 16, srcAh + 16);
            cpa16(d + OFF_AL, srcAl);     cpa16(d + OFF_AL + 16, srcAl + 16);
        }
        uint32_t d = sb + dstOffB;
        cpa16(d + OFF_BH, srcWh);         cpa16(d + OFF_BH + 16, srcWh + 16);
        cpa16(d + OFF_BL, srcWl);         cpa16(d + OFF_BL + 16, srcWl + 16);
        asm volatile("cp.async.commit_group;");
    }

    for (int c = 0; c < nChunks; c++) {
        int s = c & 1;

        asm volatile("cp.async.wait_group 0;");
        __syncthreads();

        if (c + 1 < nChunks) {
            uint32_t base = sb + (uint32_t)((s ^ 1) * SSTG);
            int cb = (c + 1) * 64;
            if (doA) {
                uint32_t d = base + dstOffA;
                cpa16(d, srcAh + cb);             cpa16(d + 16, srcAh + cb + 16);
                cpa16(d + OFF_AL, srcAl + cb);    cpa16(d + OFF_AL + 16, srcAl + cb + 16);
            }
            uint32_t d = base + dstOffB;
            cpa16(d + OFF_BH, srcWh + cb);        cpa16(d + OFF_BH + 16, srcWh + cb + 16);
            cpa16(d + OFF_BL, srcWl + cb);        cpa16(d + OFF_BL + 16, srcWl + cb + 16);
            asm volatile("cp.async.commit_group;");
        }

        uint32_t stg = sb + (uint32_t)(s * SSTG);

#pragma unroll
        for (int ks = 0; ks < 2; ks++) {
            uint32_t kb0 = (uint32_t)(ks * 32);

            uint32_t ah[2][4], al[2][4];
            ldsm4(ah[0], stg + aRow0 + kb0 + aOff);
            ldsm4(ah[1], stg + aRow0 + 16 * RSTR + kb0 + aOff);
            ldsm4(al[0], stg + OFF_AL + aRow0 + kb0 + aOff);
            ldsm4(al[1], stg + OFF_AL + aRow0 + 16 * RSTR + kb0 + aOff);

            uint32_t bh[2][4], bl[2][4];
#pragma unroll
            for (int jj = 0; jj < 2; jj++) {
                uint32_t bbase = stg + bRow0 + (uint32_t)(jj * 16 * RSTR) + kb0 + bOff;
                ldsm4(bh[jj], bbase + OFF_BH);
                ldsm4(bl[jj], bbase + OFF_BL);
            }

#pragma unroll
            for (int jj = 0; jj < 2; jj++) {
                int j0 = jj * 2, j1 = jj * 2 + 1;
                mma16816(acc[0][j0], ah[0], bh[jj][0], bh[jj][1]);
                mma16816(acc[1][j0], ah[1], bh[jj][0], bh[jj][1]);
                mma16816(acc[0][j1], ah[0], bh[jj][2], bh[jj][3]);
                mma16816(acc[1][j1], ah[1], bh[jj][2], bh[jj][3]);
            }
#pragma unroll
            for (int jj = 0; jj < 2; jj++) {
                int j0 = jj * 2, j1 = jj * 2 + 1;
                mma16816(acc[0][j0], ah[0], bl[jj][0], bl[jj][1]);
                mma16816(acc[1][j0], ah[1], bl[jj][0], bl[jj][1]);
                mma16816(acc[0][j1], ah[0], bl[jj][2], bl[jj][3]);
                mma16816(acc[1][j1], ah[1], bl[jj][2], bl[jj][3]);
            }
#pragma unroll
            for (int jj = 0; jj < 2; jj++) {
                int j0 = jj * 2, j1 = jj * 2 + 1;
                mma16816(acc[0][j0], al[0], bh[jj][0], bh[jj][1]);
                mma16816(acc[1][j0], al[1], bh[jj][0], bh[jj][1]);
                mma16816(acc[0][j1], al[0], bh[jj][2], bh[jj][3]);
                mma16816(acc[1][j1], al[1], bh[jj][2], bh[jj][3]);
            }
        }
    }

    // -------- epilogue --------
    if (Ch) {
#pragma unroll
        for (int mt = 0; mt < 2; mt++) {
            int rr = row0 + wm * 32 + mt * 16 + g;
#pragma unroll
            for (int j = 0; j < 4; j++) {
                int cc = col0 + wn * 32 + j * 8 + t * 2;
#pragma unroll
                for (int hh = 0; hh < 2; hh++) {
                    uint32_t hb, lb;
                    split2(acc[mt][j][hh * 2 + 0], acc[mt][j][hh * 2 + 1], hb, lb);
                    size_t idx = (size_t)(rr + hh * 8) * Nn + cc;
                    *(uint32_t*)(Ch + idx) = hb;
                    *(uint32_t*)(Cl + idx) = lb;
                }
            }
        }
    } else {
#pragma unroll
        for (int mt = 0; mt < 2; mt++) {
            int rr = row0 + wm * 32 + mt * 16 + g;
#pragma unroll
            for (int j = 0; j < 4; j++) {
                int cc = col0 + wn * 32 + j * 8 + t * 2;
                *(float2*)(C + (size_t)rr * Nn + cc) =
                    make_float2(acc[mt][j][0], acc[mt][j][1]);
                *(float2*)(C + (size_t)(rr + 8) * Nn + cc) =
                    make_float2(acc[mt][j][2], acc[mt][j][3]);
            }
        }
    }
}

// ---------------------------------------------------------------------------
// Split-KV HMMA flash attention, fp16 (R14, unchanged).
// QK^T: 3-product fp16 split. PV: single fp16 product.
// ---------------------------------------------------------------------------
#define FSTR   144
#define FQL    18432
#define FKV    36864
#define FKVSTG 27648
#define FKH    0
#define FKL    9216
#define FVH    18432
#define FSMEM  (36864 + 2 * 27648)   /* 92160 */

__global__ __launch_bounds__(256, 2) void flash_mma(
    const __half* __restrict__ qkvh,
    const __half* __restrict__ qkvl,
    const int* __restrict__ mask_head,
    const int* __restrict__ mask_child,
    float* __restrict__ arc,
    float* __restrict__ opart,
    float* __restrict__ pm,
    float* __restrict__ pl)
{
    extern __shared__ char fsm[];
    uint32_t sb = smem_u32(fsm);

    int tid = threadIdx.x;
    int lane = tid & 31, w = tid >> 5;
    int g = lane >> 2, t = lane & 3;
    int qm = lane >> 3, rm = lane & 7;

    int wrk = blockIdx.x;
    int split = wrk & 1;
    int qbx = 7 - (wrk >> 1);
    int qi0 = qbx * 128;
    int nT = 2 * qbx + 2;
    int t0 = split ? (qbx + 1) : 0;
    int t1 = split ? nT : (qbx + 1);

    int bhx = blockIdx.y;
    int b = bhx >> 4, h = bhx & 15;

    const int* maskp = ((h < 8) ? mask_head : mask_child) + (size_t)b * S_DIM * S_DIM;
    const __half* qh_g = qkvh + (size_t)b * S_DIM * E3 + h * DH;
    const __half* ql_g = qkvl + (size_t)b * S_DIM * E3 + h * DH;
    const char* kh_g = (const char*)(qh_g + E_DIM);
    const char* kl_g = (const char*)(ql_g + E_DIM);
    const char* vh_g = (const char*)(qh_g + 2 * E_DIM);
    const size_t rowB = (size_t)E3 * 2;

    {
        int r = tid >> 1, hf = tid & 1;
        const char* sh = (const char*)(qh_g + (size_t)(qi0 + r) * E3) + hf * 64;
        const char* sl = (const char*)(ql_g + (size_t)(qi0 + r) * E3) + hf * 64;
        uint32_t d = sb + (uint32_t)(r * FSTR + hf * 64);
#pragma unroll
        for (int i = 0; i < 4; i++) {
            cpa16(d + i * 16, sh + i * 16);
            cpa16(d + FQL + i * 16, sl + i * 16);
        }
        asm volatile("cp.async.commit_group;");
    }

    int r2 = tid >> 2, q4 = tid & 3;

    {
        size_t so = (size_t)(t0 * 64 + r2) * rowB + q4 * 32;
        uint32_t d = sb + FKV + (uint32_t)(r2 * FSTR + q4 * 32);
        cpa16(d + FKH, kh_g + so);        cpa16(d + FKH + 16, kh_g + so + 16);
        cpa16(d + FKL, kl_g + so);        cpa16(d + FKL + 16, kl_g + so + 16);
        cpa16(d + FVH, vh_g + so);        cpa16(d + FVH + 16, vh_g + so + 16);
        asm volatile("cp.async.commit_group;");
    }

    float* arcw = arc + (size_t)bhx * S_DIM * S_DIM;
    if (split == 0) {
        int zr = qi0 + (tid >> 1);
        int zc = (tid & 1) * 32;
        float4 z = make_float4(0.f, 0.f, 0.f, 0.f);
        for (int kj = nT; kj < S_DIM / 64; kj++) {
            float* p = arcw + (size_t)zr * S_DIM + kj * 64 + zc;
#pragma unroll
            for (int i = 0; i < 8; i++) *(float4*)(p + i * 4) = z;
        }
    }

    uint32_t aOff = (uint32_t)(((qm & 1) * 8 + rm) * FSTR + (qm >> 1) * 16);
    uint32_t bOff = (uint32_t)(((qm >> 1) * 8 + rm) * FSTR + (qm & 1) * 16);
    uint32_t qBase = sb + (uint32_t)(w * 16 * FSTR);

    float m0 = -1e30f, m1 = -1e30f, l0s = 0.f, l1s = 0.f;
    float oacc[8][4];
#pragma unroll
    for (int i = 0; i < 8; i++)
#pragma unroll
        for (int q = 0; q < 4; q++) oacc[i][q] = 0.f;

    int ig0 = qi0 + w * 16 + g;
    int ig1 = ig0 + 8;
    const int* mr0 = maskp + (size_t)ig0 * S_DIM;
    const int* mr1 = maskp + (size_t)ig1 * S_DIM;
    float* ar0 = arcw + (size_t)ig0 * S_DIM;
    float* ar1 = arcw + (size_t)ig1 * S_DIM;
    const float INV64 = 1.0f / 64.0f;

    for (int kj = t0; kj < t1; kj++) {
        int li = kj - t0;
        int s = li & 1;
        uint32_t kvb = sb + FKV + (uint32_t)(s * FKVSTG);

        asm volatile("cp.async.wait_group 0;");
        __syncthreads();

        if (kj + 1 < t1) {
            size_t so = (size_t)((kj + 1) * 64 + r2) * rowB + q4 * 32;
            uint32_t d = sb + FKV + (uint32_t)((s ^ 1) * FKVSTG)
                       + (uint32_t)(r2 * FSTR + q4 * 32);
            cpa16(d + FKH, kh_g + so);        cpa16(d + FKH + 16, kh_g + so + 16);
            cpa16(d + FKL, kl_g + so);        cpa16(d + FKL + 16, kl_g + so + 16);
            cpa16(d + FVH, vh_g + so);        cpa16(d + FVH + 16, vh_g + so + 16);
            asm volatile("cp.async.commit_group;");
        }

        float sc_[8][4];
#pragma unroll
        for (int i = 0; i < 8; i++)
#pragma unroll
            for (int q = 0; q < 4; q++) sc_[i][q] = 0.f;

#pragma unroll
        for (int ks = 0; ks < 4; ks++) {
            uint32_t qa = qBase + (uint32_t)(ks * 32) + aOff;
            uint32_t qh_f[4], ql_f[4];
            ldsm4(qh_f, qa);
            ldsm4(ql_f, qa + FQL);
#pragma unroll
            for (int jj = 0; jj < 4; jj++) {
                uint32_t ka = kvb + (uint32_t)(jj * 16 * FSTR + ks * 32) + bOff;
                uint32_t kh_f[4], kl_f[4];
                ldsm4(kh_f, ka + FKH);
                ldsm4(kl_f, ka + FKL);
                int j0 = jj * 2, j1 = jj * 2 + 1;
                mma16816(sc_[j0], qh_f, kh_f[0], kh_f[1]);
                mma16816(sc_[j1], qh_f, kh_f[2], kh_f[3]);
                mma16816(sc_[j0], qh_f, kl_f[0], kl_f[1]);
                mma16816(sc_[j1], qh_f, kl_f[2], kl_f[3]);
                mma16816(sc_[j0], ql_f, kh_f[0], kh_f[1]);
                mma16816(sc_[j1], ql_f, kh_f[2], kh_f[3]);
            }
        }

        int j0b = kj * 64;
        float mt0 = -1e30f, mt1 = -1e30f;
#pragma unroll
        for (int tl = 0; tl < 8; tl++) {
            int jg = j0b + tl * 8 + t * 2;
            int2 mk0 = *(const int2*)(mr0 + jg);
            int2 mk1 = *(const int2*)(mr1 + jg);
            float s00 = sc_[tl][0] * INV64;
            float s01 = sc_[tl][1] * INV64;
            float s10 = sc_[tl][2] * INV64;
            float s11 = sc_[tl][3] * INV64;
            if (!((jg     <= ig0) && mk0.x)) s00 = -1e30f;
            if (!((jg + 1 <= ig0) && mk0.y)) s01 = -1e30f;
            if (!((jg     <= ig1) && mk1.x)) s10 = -1e30f;
            if (!((jg + 1 <= ig1) && mk1.y)) s11 = -1e30f;
            float u00 = __expf(s00), u01 = __expf(s01);
            float u10 = __expf(s10), u11 = __expf(s11);
            sc_[tl][0] = u00; sc_[tl][1] = u01;
            sc_[tl][2] = u10; sc_[tl][3] = u11;
            *(float2*)(ar0 + jg) = make_float2(__fdividef(u00, 1.f + u00),
                                               __fdividef(u01, 1.f + u01));
            *(float2*)(ar1 + jg) = make_float2(__fdividef(u10, 1.f + u10),
                                               __fdividef(u11, 1.f + u11));
            mt0 = fmaxf(mt0, fmaxf(s00, s01));
            mt1 = fmaxf(mt1, fmaxf(s10, s11));
        }
        mt0 = fmaxf(mt0, __shfl_xor_sync(0xffffffffu, mt0, 1));
        mt0 = fmaxf(mt0, __shfl_xor_sync(0xffffffffu, mt0, 2));
        mt1 = fmaxf(mt1, __shfl_xor_sync(0xffffffffu, mt1, 1));
        mt1 = fmaxf(mt1, __shfl_xor_sync(0xffffffffu, mt1, 2));

        float mn0 = fmaxf(fmaxf(m0, mt0), -80.f);
        float mn1 = fmaxf(fmaxf(m1, mt1), -80.f);
        float rc0 = __expf(m0 - mn0), rc1 = __expf(m1 - mn1);
        float ce0 = __expf(-mn0), ce1 = __expf(-mn1);

        float su0 = 0.f, su1 = 0.f;
#pragma unroll
        for (int tl = 0; tl < 8; tl++) {
            su0 += sc_[tl][0] + sc_[tl][1];
            su1 += sc_[tl][2] + sc_[tl][3];
        }
        su0 += __shfl_xor_sync(0xffffffffu, su0, 1);
        su0 += __shfl_xor_sync(0xffffffffu, su0, 2);
        su1 += __shfl_xor_sync(0xffffffffu, su1, 1);
        su1 += __shfl_xor_sync(0xffffffffu, su1, 2);

        l0s = l0s * rc0 + su0 * ce0;
        l1s = l1s * rc1 + su1 * ce1;
        m0 = mn0; m1 = mn1;
#pragma unroll
        for (int nt = 0; nt < 8; nt++) {
            oacc[nt][0] *= rc0; oacc[nt][1] *= rc0;
            oacc[nt][2] *= rc1; oacc[nt][3] *= rc1;
        }

#pragma unroll
        for (int kk = 0; kk < 4; kk++) {
            int ta = 2 * kk, tb = 2 * kk + 1;
            uint32_t aP[4];
            aP[0] = h2_bits(__float22half2_rn(
                        make_float2(sc_[ta][0] * ce0, sc_[ta][1] * ce0)));
            aP[1] = h2_bits(__float22half2_rn(
                        make_float2(sc_[ta][2] * ce1, sc_[ta][3] * ce1)));
            aP[2] = h2_bits(__float22half2_rn(
                        make_float2(sc_[tb][0] * ce0, sc_[tb][1] * ce0)));
            aP[3] = h2_bits(__float22half2_rn(
                        make_float2(sc_[tb][2] * ce1, sc_[tb][3] * ce1)));

#pragma unroll
            for (int np = 0; np < 4; np++) {
                uint32_t va = kvb + (uint32_t)(kk * 16 * FSTR + np * 32) + aOff;
                uint32_t vh_f[4];
                ldsm4t(vh_f, va + FVH);
                int n0 = np * 2, n1 = np * 2 + 1;
                mma16816(oacc[n0], aP, vh_f[0], vh_f[1]);
                mma16816(oacc[n1], aP, vh_f[2], vh_f[3]);
            }
        }
    }

    float* obase = opart + (size_t)(split * B_DIM + b) * S_DIM * E_DIM;
#pragma unroll
    for (int nt = 0; nt < 8; nt++) {
        int col = h * DH + nt * 8 + t * 2;
        *(float2*)(obase + (size_t)ig0 * E_DIM + col) =
            make_float2(oacc[nt][0], oacc[nt][1]);
        *(float2*)(obase + (size_t)ig1 * E_DIM + col) =
            make_float2(oacc[nt][2], oacc[nt][3]);
    }
    if (t == 0) {
        int mi = (split * 32 + bhx) * S_DIM;
        pm[mi + ig0] = m0;  pm[mi + ig1] = m1;
        pl[mi + ig0] = l0s; pl[mi + ig1] = l1s;
    }
}

// ---------------------------------------------------------------------------
// Merge split-KV partials -> fp16 hi/lo head-out
// ---------------------------------------------------------------------------
__global__ void merge_kernel(const float* __restrict__ opart,
                             const float* __restrict__ pm,
                             const float* __restrict__ pl,
                             __half* __restrict__ hoh,
                             __half* __restrict__ hol)
{
    int i = blockIdx.x * blockDim.x + threadIdx.x;
    const int n4 = B_DIM * S_DIM * E_DIM / 4;
    if (i >= n4) return;
    int e4 = i * 4;
    int col = e4 & (E_DIM - 1);
    int s   = (e4 >> 10) & (S_DIM - 1);
    int b   = e4 >> 20;
    int h   = col >> 6;
    int mi  = ((b * 16 + h) << 10) + s;

    float m0 = pm[mi], m1 = pm[(32 << 10) + mi];
    float l0 = pl[mi], l1 = pl[(32 << 10) + mi];
    float m = fmaxf(m0, m1);
    float w0 = __expf(m0 - m), w1 = __expf(m1 - m);
    float l = l0 * w0 + l1 * w1;
    float inv = (l > 0.f) ? (1.0f / l) : 0.f;
    float s0 = w0 * inv, s1 = w1 * inv;

    size_t o0i = ((size_t)b * S_DIM + s) * E_DIM + col;
    float4 A = *(const float4*)(opart + o0i);
    float4 Bv = *(const float4*)(opart + (size_t)B_DIM * S_DIM * E_DIM + o0i);

    float o0 = A.x * s0 + Bv.x * s1;
    float o1 = A.y * s0 + Bv.y * s1;
    float o2 = A.z * s0 + Bv.z * s1;
    float o3 = A.w * s0 + Bv.w * s1;

    uint32_t h0, l0b, h1, l1b;
    split2(o0, o1, h0, l0b);
    split2(o2, o3, h1, l1b);
    *(uint2*)(hoh + e4) = make_uint2(h0, h1);
    *(uint2*)(hol + e4) = make_uint2(l0b, l1b);
}

// ---------------------------------------------------------------------------
extern "C" void kernel_launch(void* const* d_in, const int* in_sizes, int n_in,
                              void* d_out, int out_size)
{
    const float* x       = (const float*)d_in[0];
    const float* w_qkv   = (const float*)d_in[1];
    const float* w_proj  = (const float*)d_in[2];
    const int* mask_head  = (const int*)d_in[3];
    const int* mask_child = (const int*)d_in[4];

    float* out = (float*)d_out;
    float* arc = out + (size_t)B_DIM * S_DIM * E_DIM;

    __half *qkvh, *qkvl, *xh, *xl, *wqh, *wql, *wph, *wpl, *hoh, *hol;
    float *opart, *pmv, *plv;
    cudaGetSymbolAddress((void**)&qkvh, g_qkvh);
    cudaGetSymbolAddress((void**)&qkvl, g_qkvl);
    cudaGetSymbolAddress((void**)&xh, g_xh);
    cudaGetSymbolAddress((void**)&xl, g_xl);
    cudaGetSymbolAddress((void**)&wqh, g_wqh);
    cudaGetSymbolAddress((void**)&wql, g_wql);
    cudaGetSymbolAddress((void**)&wph, g_wph);
    cudaGetSymbolAddress((void**)&wpl, g_wpl);
    cudaGetSymbolAddress((void**)&hoh, g_hoh);
    cudaGetSymbolAddress((void**)&hol, g_hol);
    cudaGetSymbolAddress((void**)&opart, g_opart);
    cudaGetSymbolAddress((void**)&pmv, g_pm);
    cudaGetSymbolAddress((void**)&plv, g_pl);

    const int gemm_smem = 2 * SSTG;   // 61440 -> 3 CTAs/SM
    cudaFuncSetAttribute(gemm_bf,
                         cudaFuncAttributeMaxDynamicSharedMemorySize, gemm_smem);
    cudaFuncSetAttribute(flash_mma,
                         cudaFuncAttributeMaxDynamicSharedMemorySize, FSMEM);

    // 0) pre-split inputs into fp16 hi/lo
    {
        int n4x = (B_DIM * S_DIM * E_DIM) / 4;
        split_kernel<<<(n4x + 255) / 256, 256>>>(x, xh, xl, n4x);
        int n4q = (E3 * E_DIM) / 4;
        split_kernel<<<(n4q + 255) / 256, 256>>>(w_qkv, wqh, wql, n4q);
        int n4p = (E_DIM * E_DIM) / 4;
        split_kernel<<<(n4p + 255) / 256, 256>>>(w_proj, wph, wpl, n4p);
    }

    // 1) qkv = x @ w_qkv^T -> fp16 hi/lo directly  [64x128 tiles]
    {
        dim3 grid(E3 / 128, (B_DIM * S_DIM) / 64);
        gemm_bf<<<grid, 256, gemm_smem>>>(xh, xl, wqh, wql,
                                          nullptr, qkvh, qkvl, E3, E_DIM);
    }

    // 2) split-KV fp16 flash attention
    {
        dim3 grid(16, B_DIM * MH);
        flash_mma<<<grid, 256, FSMEM>>>(qkvh, qkvl, mask_head, mask_child,
                                        arc, opart, pmv, plv);
    }

    // 2b) merge partials -> fp16 hi/lo head-out
    {
        int n4 = (B_DIM * S_DIM * E_DIM) / 4;
        merge_kernel<<<(n4 + 255) / 256, 256>>>(opart, pmv, plv, hoh, hol);
    }

    // 3) out = headout @ w_proj^T  (fp32 final output)
    {
        dim3 grid(E_DIM / 128, (B_DIM * S_DIM) / 64);
        gemm_bf<<<grid, 256, gemm_smem>>>(hoh, hol, wph, wpl,
                                          out, nullptr, nullptr, E_DIM, E_DIM);
    }
}

// round 16
// speedup vs baseline: 1.0404x; 1.0404x over previous
#include <cuda_runtime.h>
#include <cuda_fp16.h>
#include <cstdint>

#define B_DIM 2
#define S_DIM 1024
#define E_DIM 1024
#define MH    16
#define DH    64
#define E3    3072

// Scratch (no cudaMalloc allowed) — fp16 hi/lo splits
__device__ __half g_qkvh[B_DIM * S_DIM * E3];
__device__ __half g_qkvl[B_DIM * S_DIM * E3];
__device__ __half g_xh[B_DIM * S_DIM * E_DIM];
__device__ __half g_xl[B_DIM * S_DIM * E_DIM];
__device__ __half g_wqh[E3 * E_DIM];
__device__ __half g_wql[E3 * E_DIM];
__device__ __half g_wph[E_DIM * E_DIM];
__device__ __half g_wpl[E_DIM * E_DIM];
__device__ __half g_hoh[B_DIM * S_DIM * E_DIM];
__device__ __half g_hol[B_DIM * S_DIM * E_DIM];
__device__ float g_opart[2 * B_DIM * S_DIM * E_DIM];
__device__ float g_pm[2 * 32 * S_DIM];
__device__ float g_pl[2 * 32 * S_DIM];

// LPT work-unit table: (qbx, split, t0, t1), heavy units first
__device__ const int c_qbx[12] = {7, 7, 3, 6, 6, 5, 5, 2, 4, 4, 1, 0};
__device__ const int c_spl[12] = {0, 1, 0, 0, 1, 0, 1, 0, 0, 1, 0, 0};
__device__ const int c_t0[12]  = {0, 8, 0, 0, 7, 0, 6, 0, 0, 5, 0, 0};
__device__ const int c_t1[12]  = {8, 16, 8, 7, 14, 6, 12, 6, 5, 10, 4, 2};

__device__ __forceinline__ uint32_t smem_u32(const void* p) {
    uint32_t a;
    asm("{ .reg .u64 t; cvta.to.shared.u64 t, %1; cvt.u32.u64 %0, t; }"
        : "=r"(a) : "l"(p));
    return a;
}

__device__ __forceinline__ uint32_t h2_bits(__half2 h) {
    return *reinterpret_cast<uint32_t*>(&h);
}

__device__ __forceinline__ void split2(float a, float b,
                                       uint32_t& hi, uint32_t& lo) {
    __half2 h = __float22half2_rn(make_float2(a, b));
    float2 hf = __half22float2(h);
    __half2 l = __float22half2_rn(make_float2(a - hf.x, b - hf.y));
    hi = h2_bits(h);
    lo = h2_bits(l);
}

__device__ __forceinline__ void mma16816(float* d, const uint32_t* a,
                                         uint32_t b0, uint32_t b1) {
    asm volatile(
        "mma.sync.aligned.m16n8k16.row.col.f32.f16.f16.f32 "
        "{%0,%1,%2,%3}, {%4,%5,%6,%7}, {%8,%9}, {%0,%1,%2,%3};"
        : "+f"(d[0]), "+f"(d[1]), "+f"(d[2]), "+f"(d[3])
        : "r"(a[0]), "r"(a[1]), "r"(a[2]), "r"(a[3]), "r"(b0), "r"(b1));
}

__device__ __forceinline__ void ldsm4(uint32_t* d, uint32_t addr) {
    asm volatile("ldmatrix.sync.aligned.m8n8.x4.shared.b16 {%0,%1,%2,%3}, [%4];"
        : "=r"(d[0]), "=r"(d[1]), "=r"(d[2]), "=r"(d[3]) : "r"(addr));
}

__device__ __forceinline__ void ldsm4t(uint32_t* d, uint32_t addr) {
    asm volatile("ldmatrix.sync.aligned.m8n8.x4.trans.shared.b16 {%0,%1,%2,%3}, [%4];"
        : "=r"(d[0]), "=r"(d[1]), "=r"(d[2]), "=r"(d[3]) : "r"(addr));
}

__device__ __forceinline__ void cpa16(uint32_t dst, const void* src) {
    asm volatile("cp.async.cg.shared.global [%0], [%1], 16;"
                 :: "r"(dst), "l"(src));
}

// ---------------------------------------------------------------------------
// Fused pre-pass: split x, w_qkv, w_proj fp32 -> fp16 hi/lo in one launch
// ---------------------------------------------------------------------------
#define N4X (B_DIM * S_DIM * E_DIM / 4)
#define N4Q (E3 * E_DIM / 4)
#define N4P (E_DIM * E_DIM / 4)

__global__ void split_all_kernel(const float* __restrict__ x,
                                 const float* __restrict__ wq,
                                 const float* __restrict__ wp,
                                 __half* __restrict__ xh, __half* __restrict__ xl,
                                 __half* __restrict__ wqh, __half* __restrict__ wql,
                                 __half* __restrict__ wph, __half* __restrict__ wpl)
{
    int i = blockIdx.x * blockDim.x + threadIdx.x;
    const float* in;
    __half *hi, *lo;
    int j;
    if (i < N4X)                { in = x;  hi = xh;  lo = xl;  j = i; }
    else if (i < N4X + N4Q)     { in = wq; hi = wqh; lo = wql; j = i - N4X; }
    else if (i < N4X + N4Q + N4P) { in = wp; hi = wph; lo = wpl; j = i - N4X - N4Q; }
    else return;
    float4 v = *(const float4*)(in + j * 4);
    uint32_t h0, l0, h1, l1;
    split2(v.x, v.y, h0, l0);
    split2(v.z, v.w, h1, l1);
    *(uint2*)(hi + j * 4) = make_uint2(h0, h1);
    *(uint2*)(lo + j * 4) = make_uint2(l0, l1);
}

// ---------------------------------------------------------------------------
// HMMA GEMM on pre-split fp16 (3-product). CTA 128x128, 8 warps (4x2),
// K chunk 32, 2-stage cp.async pipeline, 2 CTAs/SM.  (R14 config)
// ---------------------------------------------------------------------------
#define RSTR  80
#define TSZb  (128 * RSTR)
#define SSTG  (4 * TSZb)

__global__ __launch_bounds__(256, 2) void gemm_bf(
    const __half* __restrict__ Ah_, const __half* __restrict__ Al_,
    const __half* __restrict__ Wh_, const __half* __restrict__ Wl_,
    float* __restrict__ C,
    __half* __restrict__ Ch, __half* __restrict__ Cl,
    int Nn, int Kn)
{
    extern __shared__ char smem[];
    uint32_t sb = smem_u32(smem);

    int tid = threadIdx.x;
    int lane = tid & 31, wid = tid >> 5;
    int wm = wid >> 1, wn = wid & 1;
    int g = lane >> 2, t = lane & 3;
    int row0 = blockIdx.y * 128;
    int col0 = blockIdx.x * 128;

    int qm = lane >> 3, rm = lane & 7;
    uint32_t aOff = (uint32_t)(((qm & 1) * 8 + rm) * RSTR + (qm >> 1) * 16);
    uint32_t bOff = (uint32_t)(((qm >> 1) * 8 + rm) * RSTR + (qm & 1) * 16);

    float acc[2][8][4];
#pragma unroll
    for (int mt = 0; mt < 2; mt++)
#pragma unroll
        for (int j = 0; j < 8; j++)
#pragma unroll
            for (int q = 0; q < 4; q++) acc[mt][j][q] = 0.0f;

    int r = tid >> 1;
    int half_ = tid & 1;
    const char* srcAh = (const char*)(Ah_ + (size_t)(row0 + r) * Kn) + half_ * 32;
    const char* srcAl = (const char*)(Al_ + (size_t)(row0 + r) * Kn) + half_ * 32;
    const char* srcWh = (const char*)(Wh_ + (size_t)(col0 + r) * Kn) + half_ * 32;
    const char* srcWl = (const char*)(Wl_ + (size_t)(col0 + r) * Kn) + half_ * 32;
    uint32_t dstOff = (uint32_t)(r * RSTR + half_ * 32);

    uint32_t aRow0 = (uint32_t)((wm * 32) * RSTR);
    uint32_t bRow0 = (uint32_t)((wn * 64) * RSTR);

    int nChunks = Kn >> 5;

    {
        uint32_t base = sb + dstOff;
        cpa16(base, srcAh);               cpa16(base + 16, srcAh + 16);
        cpa16(base + TSZb, srcAl);        cpa16(base + TSZb + 16, srcAl + 16);
        cpa16(base + 2 * TSZb, srcWh);    cpa16(base + 2 * TSZb + 16, srcWh + 16);
        cpa16(base + 3 * TSZb, srcWl);    cpa16(base + 3 * TSZb + 16, srcWl + 16);
        asm volatile("cp.async.commit_group;");
    }

    for (int c = 0; c < nChunks; c++) {
        int s = c & 1;

        asm volatile("cp.async.wait_group 0;");
        __syncthreads();

        if (c + 1 < nChunks) {
            uint32_t base = sb + (uint32_t)((s ^ 1) * SSTG) + dstOff;
            int cb = (c + 1) * 64;
            cpa16(base, srcAh + cb);              cpa16(base + 16, srcAh + cb + 16);
            cpa16(base + TSZb, srcAl + cb);       cpa16(base + TSZb + 16, srcAl + cb + 16);
            cpa16(base + 2 * TSZb, srcWh + cb);   cpa16(base + 2 * TSZb + 16, srcWh + cb + 16);
            cpa16(base + 3 * TSZb, srcWl + cb);   cpa16(base + 3 * TSZb + 16, srcWl + cb + 16);
            asm volatile("cp.async.commit_group;");
        }

        uint32_t stg = sb + (uint32_t)(s * SSTG);

#pragma unroll
        for (int ks = 0; ks < 2; ks++) {
            uint32_t kb0 = (uint32_t)(ks * 32);

            uint32_t ah[2][4], al[2][4];
            ldsm4(ah[0], stg + aRow0 + kb0 + aOff);
            ldsm4(ah[1], stg + aRow0 + 16 * RSTR + kb0 + aOff);
            ldsm4(al[0], stg + TSZb + aRow0 + kb0 + aOff);
            ldsm4(al[1], stg + TSZb + aRow0 + 16 * RSTR + kb0 + aOff);

            uint32_t bh[4][4], bl[4][4];
#pragma unroll
            for (int jj = 0; jj < 4; jj++) {
                uint32_t bbase = stg + bRow0 + (uint32_t)(jj * 16 * RSTR) + kb0 + bOff;
                ldsm4(bh[jj], bbase + 2 * TSZb);
                ldsm4(bl[jj], bbase + 3 * TSZb);
            }

#pragma unroll
            for (int jj = 0; jj < 4; jj++) {
                int j0 = jj * 2, j1 = jj * 2 + 1;
                mma16816(acc[0][j0], ah[0], bh[jj][0], bh[jj][1]);
                mma16816(acc[1][j0], ah[1], bh[jj][0], bh[jj][1]);
                mma16816(acc[0][j1], ah[0], bh[jj][2], bh[jj][3]);
                mma16816(acc[1][j1], ah[1], bh[jj][2], bh[jj][3]);
            }
#pragma unroll
            for (int jj = 0; jj < 4; jj++) {
                int j0 = jj * 2, j1 = jj * 2 + 1;
                mma16816(acc[0][j0], ah[0], bl[jj][0], bl[jj][1]);
                mma16816(acc[1][j0], ah[1], bl[jj][0], bl[jj][1]);
                mma16816(acc[0][j1], ah[0], bl[jj][2], bl[jj][3]);
                mma16816(acc[1][j1], ah[1], bl[jj][2], bl[jj][3]);
            }
#pragma unroll
            for (int jj = 0; jj < 4; jj++) {
                int j0 = jj * 2, j1 = jj * 2 + 1;
                mma16816(acc[0][j0], al[0], bh[jj][0], bh[jj][1]);
                mma16816(acc[1][j0], al[1], bh[jj][0], bh[jj][1]);
                mma16816(acc[0][j1], al[0], bh[jj][2], bh[jj][3]);
                mma16816(acc[1][j1], al[1], bh[jj][2], bh[jj][3]);
            }
        }
    }

    if (Ch) {
#pragma unroll
        for (int mt = 0; mt < 2; mt++) {
            int rr = row0 + wm * 32 + mt * 16 + g;
#pragma unroll
            for (int j = 0; j < 8; j++) {
                int cc = col0 + wn * 64 + j * 8 + t * 2;
#pragma unroll
                for (int hh = 0; hh < 2; hh++) {
                    uint32_t hb, lb;
                    split2(acc[mt][j][hh * 2 + 0], acc[mt][j][hh * 2 + 1], hb, lb);
                    size_t idx = (size_t)(rr + hh * 8) * Nn + cc;
                    *(uint32_t*)(Ch + idx) = hb;
                    *(uint32_t*)(Cl + idx) = lb;
                }
            }
        }
    } else {
#pragma unroll
        for (int mt = 0; mt < 2; mt++) {
            int rr = row0 + wm * 32 + mt * 16 + g;
#pragma unroll
            for (int j = 0; j < 8; j++) {
                int cc = col0 + wn * 64 + j * 8 + t * 2;
                *(float2*)(C + (size_t)rr * Nn + cc) =
                    make_float2(acc[mt][j][0], acc[mt][j][1]);
                *(float2*)(C + (size_t)(rr + 8) * Nn + cc) =
                    make_float2(acc[mt][j][2], acc[mt][j][3]);
            }
        }
    }
}

// ---------------------------------------------------------------------------
// Split-KV fp16 flash attention with LPT work units (12 per bh).
// qb>=4: split in two halves; qb<=3: single CTA (merge passes slot0 through).
// ---------------------------------------------------------------------------
#define FSTR   144
#define FQL    18432
#define FKV    36864
#define FKVSTG 27648
#define FKH    0
#define FKL    9216
#define FVH    18432
#define FSMEM  (36864 + 2 * 27648)   /* 92160 */

__global__ __launch_bounds__(256, 2) void flash_mma(
    const __half* __restrict__ qkvh,
    const __half* __restrict__ qkvl,
    const int* __restrict__ mask_head,
    const int* __restrict__ mask_child,
    float* __restrict__ arc,
    float* __restrict__ opart,
    float* __restrict__ pm,
    float* __restrict__ pl)
{
    extern __shared__ char fsm[];
    uint32_t sb = smem_u32(fsm);

    int tid = threadIdx.x;
    int lane = tid & 31, w = tid >> 5;
    int g = lane >> 2, t = lane & 3;
    int qm = lane >> 3, rm = lane & 7;

    int wrk = blockIdx.x;             // 0..11
    int split = c_spl[wrk];
    int qbx = c_qbx[wrk];
    int t0 = c_t0[wrk];
    int t1 = c_t1[wrk];
    int qi0 = qbx * 128;
    int nT = 2 * qbx + 2;

    int bhx = blockIdx.y;
    int b = bhx >> 4, h = bhx & 15;

    const int* maskp = ((h < 8) ? mask_head : mask_child) + (size_t)b * S_DIM * S_DIM;
    const __half* qh_g = qkvh + (size_t)b * S_DIM * E3 + h * DH;
    const __half* ql_g = qkvl + (size_t)b * S_DIM * E3 + h * DH;
    const char* kh_g = (const char*)(qh_g + E_DIM);
    const char* kl_g = (const char*)(ql_g + E_DIM);
    const char* vh_g = (const char*)(qh_g + 2 * E_DIM);
    const size_t rowB = (size_t)E3 * 2;

    {
        int r = tid >> 1, hf = tid & 1;
        const char* sh = (const char*)(qh_g + (size_t)(qi0 + r) * E3) + hf * 64;
        const char* sl = (const char*)(ql_g + (size_t)(qi0 + r) * E3) + hf * 64;
        uint32_t d = sb + (uint32_t)(r * FSTR + hf * 64);
#pragma unroll
        for (int i = 0; i < 4; i++) {
            cpa16(d + i * 16, sh + i * 16);
            cpa16(d + FQL + i * 16, sl + i * 16);
        }
        asm volatile("cp.async.commit_group;");
    }

    int r2 = tid >> 2, q4 = tid & 3;

    {
        size_t so = (size_t)(t0 * 64 + r2) * rowB + q4 * 32;
        uint32_t d = sb + FKV + (uint32_t)(r2 * FSTR + q4 * 32);
        cpa16(d + FKH, kh_g + so);        cpa16(d + FKH + 16, kh_g + so + 16);
        cpa16(d + FKL, kl_g + so);        cpa16(d + FKL + 16, kl_g + so + 16);
        cpa16(d + FVH, vh_g + so);        cpa16(d + FVH + 16, vh_g + so + 16);
        asm volatile("cp.async.commit_group;");
    }

    float* arcw = arc + (size_t)bhx * S_DIM * S_DIM;
    if (split == 0) {
        int zr = qi0 + (tid >> 1);
        int zc = (tid & 1) * 32;
        float4 z = make_float4(0.f, 0.f, 0.f, 0.f);
        for (int kj = nT; kj < S_DIM / 64; kj++) {
            float* p = arcw + (size_t)zr * S_DIM + kj * 64 + zc;
#pragma unroll
            for (int i = 0; i < 8; i++) *(float4*)(p + i * 4) = z;
        }
    }

    uint32_t aOff = (uint32_t)(((qm & 1) * 8 + rm) * FSTR + (qm >> 1) * 16);
    uint32_t bOff = (uint32_t)(((qm >> 1) * 8 + rm) * FSTR + (qm & 1) * 16);
    uint32_t qBase = sb + (uint32_t)(w * 16 * FSTR);

    float m0 = -1e30f, m1 = -1e30f, l0s = 0.f, l1s = 0.f;
    float oacc[8][4];
#pragma unroll
    for (int i = 0; i < 8; i++)
#pragma unroll
        for (int q = 0; q < 4; q++) oacc[i][q] = 0.f;

    int ig0 = qi0 + w * 16 + g;
    int ig1 = ig0 + 8;
    const int* mr0 = maskp + (size_t)ig0 * S_DIM;
    const int* mr1 = maskp + (size_t)ig1 * S_DIM;
    float* ar0 = arcw + (size_t)ig0 * S_DIM;
    float* ar1 = arcw + (size_t)ig1 * S_DIM;
    const float INV64 = 1.0f / 64.0f;

    for (int kj = t0; kj < t1; kj++) {
        int li = kj - t0;
        int s = li & 1;
        uint32_t kvb = sb + FKV + (uint32_t)(s * FKVSTG);

        asm volatile("cp.async.wait_group 0;");
        __syncthreads();

        if (kj + 1 < t1) {
            size_t so = (size_t)((kj + 1) * 64 + r2) * rowB + q4 * 32;
            uint32_t d = sb + FKV + (uint32_t)((s ^ 1) * FKVSTG)
                       + (uint32_t)(r2 * FSTR + q4 * 32);
            cpa16(d + FKH, kh_g + so);        cpa16(d + FKH + 16, kh_g + so + 16);
            cpa16(d + FKL, kl_g + so);        cpa16(d + FKL + 16, kl_g + so + 16);
            cpa16(d + FVH, vh_g + so);        cpa16(d + FVH + 16, vh_g + so + 16);
            asm volatile("cp.async.commit_group;");
        }

        float sc_[8][4];
#pragma unroll
        for (int i = 0; i < 8; i++)
#pragma unroll
            for (int q = 0; q < 4; q++) sc_[i][q] = 0.f;

#pragma unroll
        for (int ks = 0; ks < 4; ks++) {
            uint32_t qa = qBase + (uint32_t)(ks * 32) + aOff;
            uint32_t qh_f[4], ql_f[4];
            ldsm4(qh_f, qa);
            ldsm4(ql_f, qa + FQL);
#pragma unroll
            for (int jj = 0; jj < 4; jj++) {
                uint32_t ka = kvb + (uint32_t)(jj * 16 * FSTR + ks * 32) + bOff;
                uint32_t kh_f[4], kl_f[4];
                ldsm4(kh_f, ka + FKH);
                ldsm4(kl_f, ka + FKL);
                int j0 = jj * 2, j1 = jj * 2 + 1;
                mma16816(sc_[j0], qh_f, kh_f[0], kh_f[1]);
                mma16816(sc_[j1], qh_f, kh_f[2], kh_f[3]);
                mma16816(sc_[j0], qh_f, kl_f[0], kl_f[1]);
                mma16816(sc_[j1], qh_f, kl_f[2], kl_f[3]);
                mma16816(sc_[j0], ql_f, kh_f[0], kh_f[1]);
                mma16816(sc_[j1], ql_f, kh_f[2], kh_f[3]);
            }
        }

        int j0b = kj * 64;
        float mt0 = -1e30f, mt1 = -1e30f;
#pragma unroll
        for (int tl = 0; tl < 8; tl++) {
            int jg = j0b + tl * 8 + t * 2;
            int2 mk0 = *(const int2*)(mr0 + jg);
            int2 mk1 = *(const int2*)(mr1 + jg);
            float s00 = sc_[tl][0] * INV64;
            float s01 = sc_[tl][1] * INV64;
            float s10 = sc_[tl][2] * INV64;
            float s11 = sc_[tl][3] * INV64;
            if (!((jg     <= ig0) && mk0.x)) s00 = -1e30f;
            if (!((jg + 1 <= ig0) && mk0.y)) s01 = -1e30f;
            if (!((jg     <= ig1) && mk1.x)) s10 = -1e30f;
            if (!((jg + 1 <= ig1) && mk1.y)) s11 = -1e30f;
            float u00 = __expf(s00), u01 = __expf(s01);
            float u10 = __expf(s10), u11 = __expf(s11);
            sc_[tl][0] = u00; sc_[tl][1] = u01;
            sc_[tl][2] = u10; sc_[tl][3] = u11;
            *(float2*)(ar0 + jg) = make_float2(__fdividef(u00, 1.f + u00),
                                               __fdividef(u01, 1.f + u01));
            *(float2*)(ar1 + jg) = make_float2(__fdividef(u10, 1.f + u10),
                                               __fdividef(u11, 1.f + u11));
            mt0 = fmaxf(mt0, fmaxf(s00, s01));
            mt1 = fmaxf(mt1, fmaxf(s10, s11));
        }
        mt0 = fmaxf(mt0, __shfl_xor_sync(0xffffffffu, mt0, 1));
        mt0 = fmaxf(mt0, __shfl_xor_sync(0xffffffffu, mt0, 2));
        mt1 = fmaxf(mt1, __shfl_xor_sync(0xffffffffu, mt1, 1));
        mt1 = fmaxf(mt1, __shfl_xor_sync(0xffffffffu, mt1, 2));

        float mn0 = fmaxf(fmaxf(m0, mt0), -80.f);
        float mn1 = fmaxf(fmaxf(m1, mt1), -80.f);
        float rc0 = __expf(m0 - mn0), rc1 = __expf(m1 - mn1);
        float ce0 = __expf(-mn0), ce1 = __expf(-mn1);

        float su0 = 0.f, su1 = 0.f;
#pragma unroll
        for (int tl = 0; tl < 8; tl++) {
            su0 += sc_[tl][0] + sc_[tl][1];
            su1 += sc_[tl][2] + sc_[tl][3];
        }
        su0 += __shfl_xor_sync(0xffffffffu, su0, 1);
        su0 += __shfl_xor_sync(0xffffffffu, su0, 2);
        su1 += __shfl_xor_sync(0xffffffffu, su1, 1);
        su1 += __shfl_xor_sync(0xffffffffu, su1, 2);

        l0s = l0s * rc0 + su0 * ce0;
        l1s = l1s * rc1 + su1 * ce1;
        m0 = mn0; m1 = mn1;
#pragma unroll
        for (int nt = 0; nt < 8; nt++) {
            oacc[nt][0] *= rc0; oacc[nt][1] *= rc0;
            oacc[nt][2] *= rc1; oacc[nt][3] *= rc1;
        }

#pragma unroll
        for (int kk = 0; kk < 4; kk++) {
            int ta = 2 * kk, tb = 2 * kk + 1;
            uint32_t aP[4];
            aP[0] = h2_bits(__float22half2_rn(
                        make_float2(sc_[ta][0] * ce0, sc_[ta][1] * ce0)));
            aP[1] = h2_bits(__float22half2_rn(
                        make_float2(sc_[ta][2] * ce1, sc_[ta][3] * ce1)));
            aP[2] = h2_bits(__float22half2_rn(
                        make_float2(sc_[tb][0] * ce0, sc_[tb][1] * ce0)));
            aP[3] = h2_bits(__float22half2_rn(
                        make_float2(sc_[tb][2] * ce1, sc_[tb][3] * ce1)));

#pragma unroll
            for (int np = 0; np < 4; np++) {
                uint32_t va = kvb + (uint32_t)(kk * 16 * FSTR + np * 32) + aOff;
                uint32_t vh_f[4];
                ldsm4t(vh_f, va + FVH);
                int n0 = np * 2, n1 = np * 2 + 1;
                mma16816(oacc[n0], aP, vh_f[0], vh_f[1]);
                mma16816(oacc[n1], aP, vh_f[2], vh_f[3]);
            }
        }
    }

    float* obase = opart + (size_t)(split * B_DIM + b) * S_DIM * E_DIM;
#pragma unroll
    for (int nt = 0; nt < 8; nt++) {
        int col = h * DH + nt * 8 + t * 2;
        *(float2*)(obase + (size_t)ig0 * E_DIM + col) =
            make_float2(oacc[nt][0], oacc[nt][1]);
        *(float2*)(obase + (size_t)ig1 * E_DIM + col) =
            make_float2(oacc[nt][2], oacc[nt][3]);
    }
    if (t == 0) {
        int mi = (split * 32 + bhx) * S_DIM;
        pm[mi + ig0] = m0;  pm[mi + ig1] = m1;
        pl[mi + ig0] = l0s; pl[mi + ig1] = l1s;
    }
}

// ---------------------------------------------------------------------------
// Merge partials -> fp16 hi/lo head-out. qb>=4: two slots; qb<=3: slot 0 only.
// ---------------------------------------------------------------------------
__global__ void merge_kernel(const float* __restrict__ opart,
                             const float* __restrict__ pm,
                             const float* __restrict__ pl,
                             __half* __restrict__ hoh,
                             __half* __restrict__ hol)
{
    int i = blockIdx.x * blockDim.x + threadIdx.x;
    const int n4 = B_DIM * S_DIM * E_DIM / 4;
    if (i >= n4) return;
    int e4 = i * 4;
    int col = e4 & (E_DIM - 1);
    int s   = (e4 >> 10) & (S_DIM - 1);
    int b   = e4 >> 20;
    int h   = col >> 6;
    int mi  = ((b * 16 + h) << 10) + s;
    int qb  = s >> 7;

    size_t o0i = ((size_t)b * S_DIM + s) * E_DIM + col;
    float o0, o1, o2, o3;

    if (qb >= 4) {
        float m0 = pm[mi], m1 = pm[(32 << 10) + mi];
        float l0 = pl[mi], l1 = pl[(32 << 10) + mi];
        float m = fmaxf(m0, m1);
        float w0 = __expf(m0 - m), w1 = __expf(m1 - m);
        float l = l0 * w0 + l1 * w1;
        float inv = (l > 0.f) ? (1.0f / l) : 0.f;
        float s0 = w0 * inv, s1 = w1 * inv;
        float4 A = *(const float4*)(opart + o0i);
        float4 Bv = *(const float4*)(opart + (size_t)B_DIM * S_DIM * E_DIM + o0i);
        o0 = A.x * s0 + Bv.x * s1;
        o1 = A.y * s0 + Bv.y * s1;
        o2 = A.z * s0 + Bv.z * s1;
        o3 = A.w * s0 + Bv.w * s1;
    } else {
        float l0 = pl[mi];
        float inv = (l0 > 0.f) ? (1.0f / l0) : 0.f;
        float4 A = *(const float4*)(opart + o0i);
        o0 = A.x * inv; o1 = A.y * inv; o2 = A.z * inv; o3 = A.w * inv;
    }

    uint32_t h0, l0b, h1, l1b;
    split2(o0, o1, h0, l0b);
    split2(o2, o3, h1, l1b);
    *(uint2*)(hoh + e4) = make_uint2(h0, h1);
    *(uint2*)(hol + e4) = make_uint2(l0b, l1b);
}

// ---------------------------------------------------------------------------
extern "C" void kernel_launch(void* const* d_in, const int* in_sizes, int n_in,
                              void* d_out, int out_size)
{
    const float* x       = (const float*)d_in[0];
    const float* w_qkv   = (const float*)d_in[1];
    const float* w_proj  = (const float*)d_in[2];
    const int* mask_head  = (const int*)d_in[3];
    const int* mask_child = (const int*)d_in[4];

    float* out = (float*)d_out;
    float* arc = out + (size_t)B_DIM * S_DIM * E_DIM;

    __half *qkvh, *qkvl, *xh, *xl, *wqh, *wql, *wph, *wpl, *hoh, *hol;
    float *opart, *pmv, *plv;
    cudaGetSymbolAddress((void**)&qkvh, g_qkvh);
    cudaGetSymbolAddress((void**)&qkvl, g_qkvl);
    cudaGetSymbolAddress((void**)&xh, g_xh);
    cudaGetSymbolAddress((void**)&xl, g_xl);
    cudaGetSymbolAddress((void**)&wqh, g_wqh);
    cudaGetSymbolAddress((void**)&wql, g_wql);
    cudaGetSymbolAddress((void**)&wph, g_wph);
    cudaGetSymbolAddress((void**)&wpl, g_wpl);
    cudaGetSymbolAddress((void**)&hoh, g_hoh);
    cudaGetSymbolAddress((void**)&hol, g_hol);
    cudaGetSymbolAddress((void**)&opart, g_opart);
    cudaGetSymbolAddress((void**)&pmv, g_pm);
    cudaGetSymbolAddress((void**)&plv, g_pl);

    const int gemm_smem = 2 * SSTG;   // 81920 -> 2 CTAs/SM
    cudaFuncSetAttribute(gemm_bf,
                         cudaFuncAttributeMaxDynamicSharedMemorySize, gemm_smem);
    cudaFuncSetAttribute(flash_mma,
                         cudaFuncAttributeMaxDynamicSharedMemorySize, FSMEM);

    // 0) fused pre-split of all fp32 inputs
    {
        int total = N4X + N4Q + N4P;
        split_all_kernel<<<(total + 255) / 256, 256>>>(
            x, w_qkv, w_proj, xh, xl, wqh, wql, wph, wpl);
    }

    // 1) qkv = x @ w_qkv^T -> fp16 hi/lo directly  [128x128 tiles]
    {
        dim3 grid(E3 / 128, (B_DIM * S_DIM) / 128);
        gemm_bf<<<grid, 256, gemm_smem>>>(xh, xl, wqh, wql,
                                          nullptr, qkvh, qkvl, E3, E_DIM);
    }

    // 2) split-KV fp16 flash attention, LPT work units
    {
        dim3 grid(12, B_DIM * MH);
        flash_mma<<<grid, 256, FSMEM>>>(qkvh, qkvl, mask_head, mask_child,
                                        arc, opart, pmv, plv);
    }

    // 2b) merge partials -> fp16 hi/lo head-out
    {
        int n4 = (B_DIM * S_DIM * E_DIM) / 4;
        merge_kernel<<<(n4 + 255) / 256, 256>>>(opart, pmv, plv, hoh, hol);
    }

    // 3) out = headout @ w_proj^T  (fp32 final output)
    {
        dim3 grid(E_DIM / 128, (B_DIM * S_DIM) / 128);
        gemm_bf<<<grid, 256, gemm_smem>>>(hoh, hol, wph, wpl,
                                          out, nullptr, nullptr, E_DIM, E_DIM);
    }
}

// round 17
// speedup vs baseline: 1.2766x; 1.2271x over previous
#include <cuda_runtime.h>
#include <cuda_fp16.h>
#include <cstdint>

#define B_DIM 2
#define S_DIM 1024
#define E_DIM 1024
#define MH    16
#define DH    64
#define E3    3072

// Scratch (no cudaMalloc allowed) — fp16 hi/lo splits
__device__ __half g_qkvh[B_DIM * S_DIM * E3];
__device__ __half g_qkvl[B_DIM * S_DIM * E3];
__device__ __half g_xh[B_DIM * S_DIM * E_DIM];
__device__ __half g_xl[B_DIM * S_DIM * E_DIM];
__device__ __half g_wqh[E3 * E_DIM];
__device__ __half g_wql[E3 * E_DIM];
__device__ __half g_wph[E_DIM * E_DIM];
__device__ __half g_wpl[E_DIM * E_DIM];
__device__ __half g_hoh[B_DIM * S_DIM * E_DIM];
__device__ __half g_hol[B_DIM * S_DIM * E_DIM];
__device__ float g_opart[2 * B_DIM * S_DIM * E_DIM];
__device__ float g_pm[2 * 32 * S_DIM];
__device__ float g_pl[2 * 32 * S_DIM];

// LPT work-unit table: (qbx, split, t0, t1), heavy units first
__device__ const int c_qbx[12] = {7, 7, 3, 6, 6, 5, 5, 2, 4, 4, 1, 0};
__device__ const int c_spl[12] = {0, 1, 0, 0, 1, 0, 1, 0, 0, 1, 0, 0};
__device__ const int c_t0[12]  = {0, 8, 0, 0, 7, 0, 6, 0, 0, 5, 0, 0};
__device__ const int c_t1[12]  = {8, 16, 8, 7, 14, 6, 12, 6, 5, 10, 4, 2};

__device__ __forceinline__ uint32_t smem_u32(const void* p) {
    uint32_t a;
    asm("{ .reg .u64 t; cvta.to.shared.u64 t, %1; cvt.u32.u64 %0, t; }"
        : "=r"(a) : "l"(p));
    return a;
}

__device__ __forceinline__ uint32_t h2_bits(__half2 h) {
    return *reinterpret_cast<uint32_t*>(&h);
}

__device__ __forceinline__ void split2(float a, float b,
                                       uint32_t& hi, uint32_t& lo) {
    __half2 h = __float22half2_rn(make_float2(a, b));
    float2 hf = __half22float2(h);
    __half2 l = __float22half2_rn(make_float2(a - hf.x, b - hf.y));
    hi = h2_bits(h);
    lo = h2_bits(l);
}

__device__ __forceinline__ void mma16816(float* d, const uint32_t* a,
                                         uint32_t b0, uint32_t b1) {
    asm volatile(
        "mma.sync.aligned.m16n8k16.row.col.f32.f16.f16.f32 "
        "{%0,%1,%2,%3}, {%4,%5,%6,%7}, {%8,%9}, {%0,%1,%2,%3};"
        : "+f"(d[0]), "+f"(d[1]), "+f"(d[2]), "+f"(d[3])
        : "r"(a[0]), "r"(a[1]), "r"(a[2]), "r"(a[3]), "r"(b0), "r"(b1));
}

__device__ __forceinline__ void ldsm4(uint32_t* d, uint32_t addr) {
    asm volatile("ldmatrix.sync.aligned.m8n8.x4.shared.b16 {%0,%1,%2,%3}, [%4];"
        : "=r"(d[0]), "=r"(d[1]), "=r"(d[2]), "=r"(d[3]) : "r"(addr));
}

__device__ __forceinline__ void ldsm4t(uint32_t* d, uint32_t addr) {
    asm volatile("ldmatrix.sync.aligned.m8n8.x4.trans.shared.b16 {%0,%1,%2,%3}, [%4];"
        : "=r"(d[0]), "=r"(d[1]), "=r"(d[2]), "=r"(d[3]) : "r"(addr));
}

__device__ __forceinline__ void cpa16(uint32_t dst, const void* src) {
    asm volatile("cp.async.cg.shared.global [%0], [%1], 16;"
                 :: "r"(dst), "l"(src));
}

// ---------------------------------------------------------------------------
// Fused pre-pass: split x, w_qkv, w_proj fp32 -> fp16 hi/lo in one launch
// ---------------------------------------------------------------------------
#define N4X (B_DIM * S_DIM * E_DIM / 4)
#define N4Q (E3 * E_DIM / 4)
#define N4P (E_DIM * E_DIM / 4)

__global__ void split_all_kernel(const float* __restrict__ x,
                                 const float* __restrict__ wq,
                                 const float* __restrict__ wp,
                                 __half* __restrict__ xh, __half* __restrict__ xl,
                                 __half* __restrict__ wqh, __half* __restrict__ wql,
                                 __half* __restrict__ wph, __half* __restrict__ wpl)
{
    int i = blockIdx.x * blockDim.x + threadIdx.x;
    const float* in;
    __half *hi, *lo;
    int j;
    if (i < N4X)                { in = x;  hi = xh;  lo = xl;  j = i; }
    else if (i < N4X + N4Q)     { in = wq; hi = wqh; lo = wql; j = i - N4X; }
    else if (i < N4X + N4Q + N4P) { in = wp; hi = wph; lo = wpl; j = i - N4X - N4Q; }
    else return;
    float4 v = *(const float4*)(in + j * 4);
    uint32_t h0, l0, h1, l1;
    split2(v.x, v.y, h0, l0);
    split2(v.z, v.w, h1, l1);
    *(uint2*)(hi + j * 4) = make_uint2(h0, h1);
    *(uint2*)(lo + j * 4) = make_uint2(l0, l1);
}

// ---------------------------------------------------------------------------
// HMMA GEMM on pre-split fp16. CTA 128x128, 8 warps (4x2), K chunk 32,
// 2-stage cp.async pipeline, 2 CTAs/SM.
// WL=true: 3-product (A split x B split, hl+lh cross terms).
// WL=false: 2-product (A split x B plain fp16) — B rounding error ~2^-12.
// ---------------------------------------------------------------------------
#define RSTR  80
#define TSZb  (128 * RSTR)

template<bool WL>
__global__ __launch_bounds__(256, 2) void gemm_bf(
    const __half* __restrict__ Ah_, const __half* __restrict__ Al_,
    const __half* __restrict__ Wh_, const __half* __restrict__ Wl_,
    float* __restrict__ C,
    __half* __restrict__ Ch, __half* __restrict__ Cl,
    int Nn, int Kn)
{
    constexpr int SSTG = WL ? 4 * TSZb : 3 * TSZb;
    extern __shared__ char smem[];
    uint32_t sb = smem_u32(smem);

    int tid = threadIdx.x;
    int lane = tid & 31, wid = tid >> 5;
    int wm = wid >> 1, wn = wid & 1;
    int g = lane >> 2, t = lane & 3;
    int row0 = blockIdx.y * 128;
    int col0 = blockIdx.x * 128;

    int qm = lane >> 3, rm = lane & 7;
    uint32_t aOff = (uint32_t)(((qm & 1) * 8 + rm) * RSTR + (qm >> 1) * 16);
    uint32_t bOff = (uint32_t)(((qm >> 1) * 8 + rm) * RSTR + (qm & 1) * 16);

    float acc[2][8][4];
#pragma unroll
    for (int mt = 0; mt < 2; mt++)
#pragma unroll
        for (int j = 0; j < 8; j++)
#pragma unroll
            for (int q = 0; q < 4; q++) acc[mt][j][q] = 0.0f;

    int r = tid >> 1;
    int half_ = tid & 1;
    const char* srcAh = (const char*)(Ah_ + (size_t)(row0 + r) * Kn) + half_ * 32;
    const char* srcAl = (const char*)(Al_ + (size_t)(row0 + r) * Kn) + half_ * 32;
    const char* srcWh = (const char*)(Wh_ + (size_t)(col0 + r) * Kn) + half_ * 32;
    const char* srcWl = (const char*)(Wl_ + (size_t)(col0 + r) * Kn) + half_ * 32;
    uint32_t dstOff = (uint32_t)(r * RSTR + half_ * 32);

    uint32_t aRow0 = (uint32_t)((wm * 32) * RSTR);
    uint32_t bRow0 = (uint32_t)((wn * 64) * RSTR);

    int nChunks = Kn >> 5;

    {
        uint32_t base = sb + dstOff;
        cpa16(base, srcAh);               cpa16(base + 16, srcAh + 16);
        cpa16(base + TSZb, srcAl);        cpa16(base + TSZb + 16, srcAl + 16);
        cpa16(base + 2 * TSZb, srcWh);    cpa16(base + 2 * TSZb + 16, srcWh + 16);
        if (WL) {
            cpa16(base + 3 * TSZb, srcWl);
            cpa16(base + 3 * TSZb + 16, srcWl + 16);
        }
        asm volatile("cp.async.commit_group;");
    }

    for (int c = 0; c < nChunks; c++) {
        int s = c & 1;

        asm volatile("cp.async.wait_group 0;");
        __syncthreads();

        if (c + 1 < nChunks) {
            uint32_t base = sb + (uint32_t)((s ^ 1) * SSTG) + dstOff;
            int cb = (c + 1) * 64;
            cpa16(base, srcAh + cb);              cpa16(base + 16, srcAh + cb + 16);
            cpa16(base + TSZb, srcAl + cb);       cpa16(base + TSZb + 16, srcAl + cb + 16);
            cpa16(base + 2 * TSZb, srcWh + cb);   cpa16(base + 2 * TSZb + 16, srcWh + cb + 16);
            if (WL) {
                cpa16(base + 3 * TSZb, srcWl + cb);
                cpa16(base + 3 * TSZb + 16, srcWl + cb + 16);
            }
            asm volatile("cp.async.commit_group;");
        }

        uint32_t stg = sb + (uint32_t)(s * SSTG);

#pragma unroll
        for (int ks = 0; ks < 2; ks++) {
            uint32_t kb0 = (uint32_t)(ks * 32);

            uint32_t ah[2][4], al[2][4];
            ldsm4(ah[0], stg + aRow0 + kb0 + aOff);
            ldsm4(ah[1], stg + aRow0 + 16 * RSTR + kb0 + aOff);
            ldsm4(al[0], stg + TSZb + aRow0 + kb0 + aOff);
            ldsm4(al[1], stg + TSZb + aRow0 + 16 * RSTR + kb0 + aOff);

            uint32_t bh[4][4], bl[4][4];
#pragma unroll
            for (int jj = 0; jj < 4; jj++) {
                uint32_t bbase = stg + bRow0 + (uint32_t)(jj * 16 * RSTR) + kb0 + bOff;
                ldsm4(bh[jj], bbase + 2 * TSZb);
                if (WL) ldsm4(bl[jj], bbase + 3 * TSZb);
            }

#pragma unroll
            for (int jj = 0; jj < 4; jj++) {
                int j0 = jj * 2, j1 = jj * 2 + 1;
                mma16816(acc[0][j0], ah[0], bh[jj][0], bh[jj][1]);
                mma16816(acc[1][j0], ah[1], bh[jj][0], bh[jj][1]);
                mma16816(acc[0][j1], ah[0], bh[jj][2], bh[jj][3]);
                mma16816(acc[1][j1], ah[1], bh[jj][2], bh[jj][3]);
            }
            if (WL) {
#pragma unroll
                for (int jj = 0; jj < 4; jj++) {
                    int j0 = jj * 2, j1 = jj * 2 + 1;
                    mma16816(acc[0][j0], ah[0], bl[jj][0], bl[jj][1]);
                    mma16816(acc[1][j0], ah[1], bl[jj][0], bl[jj][1]);
                    mma16816(acc[0][j1], ah[0], bl[jj][2], bl[jj][3]);
                    mma16816(acc[1][j1], ah[1], bl[jj][2], bl[jj][3]);
                }
            }
#pragma unroll
            for (int jj = 0; jj < 4; jj++) {
                int j0 = jj * 2, j1 = jj * 2 + 1;
                mma16816(acc[0][j0], al[0], bh[jj][0], bh[jj][1]);
                mma16816(acc[1][j0], al[1], bh[jj][0], bh[jj][1]);
                mma16816(acc[0][j1], al[0], bh[jj][2], bh[jj][3]);
                mma16816(acc[1][j1], al[1], bh[jj][2], bh[jj][3]);
            }
        }
    }

    if (Ch) {
#pragma unroll
        for (int mt = 0; mt < 2; mt++) {
            int rr = row0 + wm * 32 + mt * 16 + g;
#pragma unroll
            for (int j = 0; j < 8; j++) {
                int cc = col0 + wn * 64 + j * 8 + t * 2;
#pragma unroll
                for (int hh = 0; hh < 2; hh++) {
                    uint32_t hb, lb;
                    split2(acc[mt][j][hh * 2 + 0], acc[mt][j][hh * 2 + 1], hb, lb);
                    size_t idx = (size_t)(rr + hh * 8) * Nn + cc;
                    *(uint32_t*)(Ch + idx) = hb;
                    *(uint32_t*)(Cl + idx) = lb;
                }
            }
        }
    } else {
#pragma unroll
        for (int mt = 0; mt < 2; mt++) {
            int rr = row0 + wm * 32 + mt * 16 + g;
#pragma unroll
            for (int j = 0; j < 8; j++) {
                int cc = col0 + wn * 64 + j * 8 + t * 2;
                *(float2*)(C + (size_t)rr * Nn + cc) =
                    make_float2(acc[mt][j][0], acc[mt][j][1]);
                *(float2*)(C + (size_t)(rr + 8) * Nn + cc) =
                    make_float2(acc[mt][j][2], acc[mt][j][3]);
            }
        }
    }
}

// ---------------------------------------------------------------------------
// Split-KV fp16 flash attention, LPT work units.
// QK^T: 2-product (Q split, K plain fp16). PV: single fp16 product.
// ---------------------------------------------------------------------------
#define FSTR   144
#define FQL    18432
#define FKV    36864
#define FKVSTG 18432
#define FKH    0
#define FVH    9216
#define FSMEM  (36864 + 2 * 18432)   /* 73728 */

__global__ __launch_bounds__(256, 2) void flash_mma(
    const __half* __restrict__ qkvh,
    const __half* __restrict__ qkvl,
    const int* __restrict__ mask_head,
    const int* __restrict__ mask_child,
    float* __restrict__ arc,
    float* __restrict__ opart,
    float* __restrict__ pm,
    float* __restrict__ pl)
{
    extern __shared__ char fsm[];
    uint32_t sb = smem_u32(fsm);

    int tid = threadIdx.x;
    int lane = tid & 31, w = tid >> 5;
    int g = lane >> 2, t = lane & 3;
    int qm = lane >> 3, rm = lane & 7;

    int wrk = blockIdx.x;             // 0..11
    int split = c_spl[wrk];
    int qbx = c_qbx[wrk];
    int t0 = c_t0[wrk];
    int t1 = c_t1[wrk];
    int qi0 = qbx * 128;
    int nT = 2 * qbx + 2;

    int bhx = blockIdx.y;
    int b = bhx >> 4, h = bhx & 15;

    const int* maskp = ((h < 8) ? mask_head : mask_child) + (size_t)b * S_DIM * S_DIM;
    const __half* qh_g = qkvh + (size_t)b * S_DIM * E3 + h * DH;
    const __half* ql_g = qkvl + (size_t)b * S_DIM * E3 + h * DH;
    const char* kh_g = (const char*)(qh_g + E_DIM);
    const char* vh_g = (const char*)(qh_g + 2 * E_DIM);
    const size_t rowB = (size_t)E3 * 2;

    {
        int r = tid >> 1, hf = tid & 1;
        const char* sh = (const char*)(qh_g + (size_t)(qi0 + r) * E3) + hf * 64;
        const char* sl = (const char*)(ql_g + (size_t)(qi0 + r) * E3) + hf * 64;
        uint32_t d = sb + (uint32_t)(r * FSTR + hf * 64);
#pragma unroll
        for (int i = 0; i < 4; i++) {
            cpa16(d + i * 16, sh + i * 16);
            cpa16(d + FQL + i * 16, sl + i * 16);
        }
        asm volatile("cp.async.commit_group;");
    }

    int r2 = tid >> 2, q4 = tid & 3;

    {
        size_t so = (size_t)(t0 * 64 + r2) * rowB + q4 * 32;
        uint32_t d = sb + FKV + (uint32_t)(r2 * FSTR + q4 * 32);
        cpa16(d + FKH, kh_g + so);        cpa16(d + FKH + 16, kh_g + so + 16);
        cpa16(d + FVH, vh_g + so);        cpa16(d + FVH + 16, vh_g + so + 16);
        asm volatile("cp.async.commit_group;");
    }

    float* arcw = arc + (size_t)bhx * S_DIM * S_DIM;
    if (split == 0) {
        int zr = qi0 + (tid >> 1);
        int zc = (tid & 1) * 32;
        float4 z = make_float4(0.f, 0.f, 0.f, 0.f);
        for (int kj = nT; kj < S_DIM / 64; kj++) {
            float* p = arcw + (size_t)zr * S_DIM + kj * 64 + zc;
#pragma unroll
            for (int i = 0; i < 8; i++) *(float4*)(p + i * 4) = z;
        }
    }

    uint32_t aOff = (uint32_t)(((qm & 1) * 8 + rm) * FSTR + (qm >> 1) * 16);
    uint32_t bOff = (uint32_t)(((qm >> 1) * 8 + rm) * FSTR + (qm & 1) * 16);
    uint32_t qBase = sb + (uint32_t)(w * 16 * FSTR);

    float m0 = -1e30f, m1 = -1e30f, l0s = 0.f, l1s = 0.f;
    float oacc[8][4];
#pragma unroll
    for (int i = 0; i < 8; i++)
#pragma unroll
        for (int q = 0; q < 4; q++) oacc[i][q] = 0.f;

    int ig0 = qi0 + w * 16 + g;
    int ig1 = ig0 + 8;
    const int* mr0 = maskp + (size_t)ig0 * S_DIM;
    const int* mr1 = maskp + (size_t)ig1 * S_DIM;
    float* ar0 = arcw + (size_t)ig0 * S_DIM;
    float* ar1 = arcw + (size_t)ig1 * S_DIM;
    const float INV64 = 1.0f / 64.0f;

    for (int kj = t0; kj < t1; kj++) {
        int li = kj - t0;
        int s = li & 1;
        uint32_t kvb = sb + FKV + (uint32_t)(s * FKVSTG);

        asm volatile("cp.async.wait_group 0;");
        __syncthreads();

        if (kj + 1 < t1) {
            size_t so = (size_t)((kj + 1) * 64 + r2) * rowB + q4 * 32;
            uint32_t d = sb + FKV + (uint32_t)((s ^ 1) * FKVSTG)
                       + (uint32_t)(r2 * FSTR + q4 * 32);
            cpa16(d + FKH, kh_g + so);        cpa16(d + FKH + 16, kh_g + so + 16);
            cpa16(d + FVH, vh_g + so);        cpa16(d + FVH + 16, vh_g + so + 16);
            asm volatile("cp.async.commit_group;");
        }

        // ---- QK^T: 2-product (Q split, K plain) ----
        float sc_[8][4];
#pragma unroll
        for (int i = 0; i < 8; i++)
#pragma unroll
            for (int q = 0; q < 4; q++) sc_[i][q] = 0.f;

#pragma unroll
        for (int ks = 0; ks < 4; ks++) {
            uint32_t qa = qBase + (uint32_t)(ks * 32) + aOff;
            uint32_t qh_f[4], ql_f[4];
            ldsm4(qh_f, qa);
            ldsm4(ql_f, qa + FQL);
#pragma unroll
            for (int jj = 0; jj < 4; jj++) {
                uint32_t ka = kvb + (uint32_t)(jj * 16 * FSTR + ks * 32) + bOff;
                uint32_t kh_f[4];
                ldsm4(kh_f, ka + FKH);
                int j0 = jj * 2, j1 = jj * 2 + 1;
                mma16816(sc_[j0], qh_f, kh_f[0], kh_f[1]);
                mma16816(sc_[j1], qh_f, kh_f[2], kh_f[3]);
                mma16816(sc_[j0], ql_f, kh_f[0], kh_f[1]);
                mma16816(sc_[j1], ql_f, kh_f[2], kh_f[3]);
            }
        }

        int j0b = kj * 64;
        float mt0 = -1e30f, mt1 = -1e30f;
#pragma unroll
        for (int tl = 0; tl < 8; tl++) {
            int jg = j0b + tl * 8 + t * 2;
            int2 mk0 = *(const int2*)(mr0 + jg);
            int2 mk1 = *(const int2*)(mr1 + jg);
            float s00 = sc_[tl][0] * INV64;
            float s01 = sc_[tl][1] * INV64;
            float s10 = sc_[tl][2] * INV64;
            float s11 = sc_[tl][3] * INV64;
            if (!((jg     <= ig0) && mk0.x)) s00 = -1e30f;
            if (!((jg + 1 <= ig0) && mk0.y)) s01 = -1e30f;
            if (!((jg     <= ig1) && mk1.x)) s10 = -1e30f;
            if (!((jg + 1 <= ig1) && mk1.y)) s11 = -1e30f;
            float u00 = __expf(s00), u01 = __expf(s01);
            float u10 = __expf(s10), u11 = __expf(s11);
            sc_[tl][0] = u00; sc_[tl][1] = u01;
            sc_[tl][2] = u10; sc_[tl][3] = u11;
            *(float2*)(ar0 + jg) = make_float2(__fdividef(u00, 1.f + u00),
                                               __fdividef(u01, 1.f + u01));
            *(float2*)(ar1 + jg) = make_float2(__fdividef(u10, 1.f + u10),
                                               __fdividef(u11, 1.f + u11));
            mt0 = fmaxf(mt0, fmaxf(s00, s01));
            mt1 = fmaxf(mt1, fmaxf(s10, s11));
        }
        mt0 = fmaxf(mt0, __shfl_xor_sync(0xffffffffu, mt0, 1));
        mt0 = fmaxf(mt0, __shfl_xor_sync(0xffffffffu, mt0, 2));
        mt1 = fmaxf(mt1, __shfl_xor_sync(0xffffffffu, mt1, 1));
        mt1 = fmaxf(mt1, __shfl_xor_sync(0xffffffffu, mt1, 2));

        float mn0 = fmaxf(fmaxf(m0, mt0), -80.f);
        float mn1 = fmaxf(fmaxf(m1, mt1), -80.f);
        float rc0 = __expf(m0 - mn0), rc1 = __expf(m1 - mn1);
        float ce0 = __expf(-mn0), ce1 = __expf(-mn1);

        float su0 = 0.f, su1 = 0.f;
#pragma unroll
        for (int tl = 0; tl < 8; tl++) {
            su0 += sc_[tl][0] + sc_[tl][1];
            su1 += sc_[tl][2] + sc_[tl][3];
        }
        su0 += __shfl_xor_sync(0xffffffffu, su0, 1);
        su0 += __shfl_xor_sync(0xffffffffu, su0, 2);
        su1 += __shfl_xor_sync(0xffffffffu, su1, 1);
        su1 += __shfl_xor_sync(0xffffffffu, su1, 2);

        l0s = l0s * rc0 + su0 * ce0;
        l1s = l1s * rc1 + su1 * ce1;
        m0 = mn0; m1 = mn1;
#pragma unroll
        for (int nt = 0; nt < 8; nt++) {
            oacc[nt][0] *= rc0; oacc[nt][1] *= rc0;
            oacc[nt][2] *= rc1; oacc[nt][3] *= rc1;
        }

#pragma unroll
        for (int kk = 0; kk < 4; kk++) {
            int ta = 2 * kk, tb = 2 * kk + 1;
            uint32_t aP[4];
            aP[0] = h2_bits(__float22half2_rn(
                        make_float2(sc_[ta][0] * ce0, sc_[ta][1] * ce0)));
            aP[1] = h2_bits(__float22half2_rn(
                        make_float2(sc_[ta][2] * ce1, sc_[ta][3] * ce1)));
            aP[2] = h2_bits(__float22half2_rn(
                        make_float2(sc_[tb][0] * ce0, sc_[tb][1] * ce0)));
            aP[3] = h2_bits(__float22half2_rn(
                        make_float2(sc_[tb][2] * ce1, sc_[tb][3] * ce1)));

#pragma unroll
            for (int np = 0; np < 4; np++) {
                uint32_t va = kvb + (uint32_t)(kk * 16 * FSTR + np * 32) + aOff;
                uint32_t vh_f[4];
                ldsm4t(vh_f, va + FVH);
                int n0 = np * 2, n1 = np * 2 + 1;
                mma16816(oacc[n0], aP, vh_f[0], vh_f[1]);
                mma16816(oacc[n1], aP, vh_f[2], vh_f[3]);
            }
        }
    }

    float* obase = opart + (size_t)(split * B_DIM + b) * S_DIM * E_DIM;
#pragma unroll
    for (int nt = 0; nt < 8; nt++) {
        int col = h * DH + nt * 8 + t * 2;
        *(float2*)(obase + (size_t)ig0 * E_DIM + col) =
            make_float2(oacc[nt][0], oacc[nt][1]);
        *(float2*)(obase + (size_t)ig1 * E_DIM + col) =
            make_float2(oacc[nt][2], oacc[nt][3]);
    }
    if (t == 0) {
        int mi = (split * 32 + bhx) * S_DIM;
        pm[mi + ig0] = m0;  pm[mi + ig1] = m1;
        pl[mi + ig0] = l0s; pl[mi + ig1] = l1s;
    }
}

// ---------------------------------------------------------------------------
// Merge partials -> fp16 hi/lo head-out. qb>=4: two slots; qb<=3: slot 0 only.
// ---------------------------------------------------------------------------
__global__ void merge_kernel(const float* __restrict__ opart,
                             const float* __restrict__ pm,
                             const float* __restrict__ pl,
                             __half* __restrict__ hoh,
                             __half* __restrict__ hol)
{
    int i = blockIdx.x * blockDim.x + threadIdx.x;
    const int n4 = B_DIM * S_DIM * E_DIM / 4;
    if (i >= n4) return;
    int e4 = i * 4;
    int col = e4 & (E_DIM - 1);
    int s   = (e4 >> 10) & (S_DIM - 1);
    int b   = e4 >> 20;
    int h   = col >> 6;
    int mi  = ((b * 16 + h) << 10) + s;
    int qb  = s >> 7;

    size_t o0i = ((size_t)b * S_DIM + s) * E_DIM + col;
    float o0, o1, o2, o3;

    if (qb >= 4) {
        float m0 = pm[mi], m1 = pm[(32 << 10) + mi];
        float l0 = pl[mi], l1 = pl[(32 << 10) + mi];
        float m = fmaxf(m0, m1);
        float w0 = __expf(m0 - m), w1 = __expf(m1 - m);
        float l = l0 * w0 + l1 * w1;
        float inv = (l > 0.f) ? (1.0f / l) : 0.f;
        float s0 = w0 * inv, s1 = w1 * inv;
        float4 A = *(const float4*)(opart + o0i);
        float4 Bv = *(const float4*)(opart + (size_t)B_DIM * S_DIM * E_DIM + o0i);
        o0 = A.x * s0 + Bv.x * s1;
        o1 = A.y * s0 + Bv.y * s1;
        o2 = A.z * s0 + Bv.z * s1;
        o3 = A.w * s0 + Bv.w * s1;
    } else {
        float l0 = pl[mi];
        float inv = (l0 > 0.f) ? (1.0f / l0) : 0.f;
        float4 A = *(const float4*)(opart + o0i);
        o0 = A.x * inv; o1 = A.y * inv; o2 = A.z * inv; o3 = A.w * inv;
    }

    uint32_t h0, l0b, h1, l1b;
    split2(o0, o1, h0, l0b);
    split2(o2, o3, h1, l1b);
    *(uint2*)(hoh + e4) = make_uint2(h0, h1);
    *(uint2*)(hol + e4) = make_uint2(l0b, l1b);
}

// ---------------------------------------------------------------------------
extern "C" void kernel_launch(void* const* d_in, const int* in_sizes, int n_in,
                              void* d_out, int out_size)
{
    const float* x       = (const float*)d_in[0];
    const float* w_qkv   = (const float*)d_in[1];
    const float* w_proj  = (const float*)d_in[2];
    const int* mask_head  = (const int*)d_in[3];
    const int* mask_child = (const int*)d_in[4];

    float* out = (float*)d_out;
    float* arc = out + (size_t)B_DIM * S_DIM * E_DIM;

    __half *qkvh, *qkvl, *xh, *xl, *wqh, *wql, *wph, *wpl, *hoh, *hol;
    float *opart, *pmv, *plv;
    cudaGetSymbolAddress((void**)&qkvh, g_qkvh);
    cudaGetSymbolAddress((void**)&qkvl, g_qkvl);
    cudaGetSymbolAddress((void**)&xh, g_xh);
    cudaGetSymbolAddress((void**)&xl, g_xl);
    cudaGetSymbolAddress((void**)&wqh, g_wqh);
    cudaGetSymbolAddress((void**)&wql, g_wql);
    cudaGetSymbolAddress((void**)&wph, g_wph);
    cudaGetSymbolAddress((void**)&wpl, g_wpl);
    cudaGetSymbolAddress((void**)&hoh, g_hoh);
    cudaGetSymbolAddress((void**)&hol, g_hol);
    cudaGetSymbolAddress((void**)&opart, g_opart);
    cudaGetSymbolAddress((void**)&pmv, g_pm);
    cudaGetSymbolAddress((void**)&plv, g_pl);

    const int gemm_smem2 = 2 * 3 * TSZb;   // 61440, 2-product
    const int gemm_smem3 = 2 * 4 * TSZb;   // 81920, 3-product
    cudaFuncSetAttribute(gemm_bf<false>,
                         cudaFuncAttributeMaxDynamicSharedMemorySize, gemm_smem2);
    cudaFuncSetAttribute(gemm_bf<true>,
                         cudaFuncAttributeMaxDynamicSharedMemorySize, gemm_smem3);
    cudaFuncSetAttribute(flash_mma,
                         cudaFuncAttributeMaxDynamicSharedMemorySize, FSMEM);

    // 0) fused pre-split of all fp32 inputs
    {
        int total = N4X + N4Q + N4P;
        split_all_kernel<<<(total + 255) / 256, 256>>>(
            x, w_qkv, w_proj, xh, xl, wqh, wql, wph, wpl);
    }

    // 1) qkv = x @ w_qkv^T -> fp16 hi/lo  [2-product: w_qkv plain fp16]
    {
        dim3 grid(E3 / 128, (B_DIM * S_DIM) / 128);
        gemm_bf<false><<<grid, 256, gemm_smem2>>>(xh, xl, wqh, nullptr,
                                                  nullptr, qkvh, qkvl, E3, E_DIM);
    }

    // 2) split-KV fp16 flash attention (2-product QK^T, plain-V PV)
    {
        dim3 grid(12, B_DIM * MH);
        flash_mma<<<grid, 256, FSMEM>>>(qkvh, qkvl, mask_head, mask_child,
                                        arc, opart, pmv, plv);
    }

    // 2b) merge partials -> fp16 hi/lo head-out
    {
        int n4 = (B_DIM * S_DIM * E_DIM) / 4;
        merge_kernel<<<(n4 + 255) / 256, 256>>>(opart, pmv, plv, hoh, hol);
    }

    // 3) out = headout @ w_proj^T  (3-product, fp32 final output)
    {
        dim3 grid(E_DIM / 128, (B_DIM * S_DIM) / 128);
        gemm_bf<true><<<grid, 256, gemm_smem3>>>(hoh, hol, wph, wpl,
                                                 out, nullptr, nullptr, E_DIM, E_DIM);
    }
}